// round 12
// baseline (speedup 1.0000x reference)
#include <cuda_runtime.h>

#define B_ROWS 32768
#define D_IN   200
#define K_SAMP 10
#define TM     32
#define APAD   36

__device__ float g_logits[(size_t)B_ROWS * D_IN];

// smem (floats): XsT[200][36] | H1T[100][36] (layer2 in-place) | WS double-buffer
// Slots sized for PADDED columns (reads go up to col 127 / 223; values discarded).
#define OFF_X  0
#define OFF_H1 (200 * APAD)              // 7200
#define OFF_WS (OFF_H1 + 100 * APAD)     // 10800
#define WSL12  1280                      // 128 cols * BK(10)
#define WSL3   2240                      // 224 cols * BK(10); 2x2240 <= 7200 over OFF_X
#define SMEM_FLOATS (OFF_WS + 2 * WSL12) // 13360 floats = 53440 B -> 4 CTAs/SM

typedef unsigned long long ull;

__device__ __forceinline__ ull pack2(float lo, float hi) {
    ull r; asm("mov.b64 %0, {%1, %2};" : "=l"(r) : "f"(lo), "f"(hi)); return r;
}
__device__ __forceinline__ ull dup2(float w) {
    ull r; asm("mov.b64 %0, {%1, %1};" : "=l"(r) : "f"(w)); return r;
}
__device__ __forceinline__ void unpack2(ull v, float& lo, float& hi) {
    asm("mov.b64 {%0, %1}, %2;" : "=f"(lo), "=f"(hi) : "l"(v));
}
__device__ __forceinline__ ull fma2(ull a, ull b, ull c) {
    ull d; asm("fma.rn.f32x2 %0, %1, %2, %3;" : "=l"(d) : "l"(a), "l"(b), "l"(c)); return d;
}
__device__ __forceinline__ ull mul2(ull a, ull b) {
    ull d; asm("mul.rn.f32x2 %0, %1, %2;" : "=l"(d) : "l"(a), "l"(b)); return d;
}
__device__ __forceinline__ ull add2(ull a, ull b) {
    ull d; asm("add.rn.f32x2 %0, %1, %2;" : "=l"(d) : "l"(a), "l"(b)); return d;
}
__device__ __forceinline__ float frcp(float x) {
    float r; asm("rcp.approx.f32 %0, %1;" : "=f"(r) : "f"(x)); return r;
}
__device__ __forceinline__ float flg2(float x) {
    float r; asm("lg2.approx.f32 %0, %1;" : "=f"(r) : "f"(x)); return r;
}

// ---- one layer over 32 rows; A in smem [K][APAD]; 8 warps x 4 rows ----
// Weight double-buffer at smem[WOFF], slot stride WSL floats (>= 32*CI*BK!).
template <int K, int N, int CI, int BK, int WOFF, int WSL, bool RELU, bool TOGLOBAL>
__device__ __forceinline__ void layer(float* smem, const float* Asm,
                                      const float* __restrict__ Wg,
                                      const float* __restrict__ bg,
                                      float* Hsm, float* __restrict__ Gout,
                                      int tid) {
    static_assert(BK % 2 == 0, "BK must be even (float2 weight loads)");
    static_assert(32 * CI * BK <= WSL, "slot must cover padded columns");
    constexpr int NLD = (BK * N + 255) / 256;
    constexpr int NCH = K / BK;
    const int lane = tid & 31;
    const int wy = tid >> 5;   // rows [4wy, 4wy+4)

    ull acc[2][CI];
#pragma unroll
    for (int r = 0; r < 2; r++)
#pragma unroll
        for (int c = 0; c < CI; c++) acc[r][c] = 0ull;

    float pf[NLD];
#pragma unroll
    for (int i = 0; i < NLD; i++) {
        int idx = tid + 256 * i;
        if (idx < BK * N) pf[i] = Wg[idx];
    }
    __syncthreads();   // prev layer done with this region & Asm writes visible
    {
        float* ws0 = smem + WOFF;
#pragma unroll
        for (int i = 0; i < NLD; i++) {
            int idx = tid + 256 * i;
            if (idx < BK * N) { int kk = idx / N, c = idx - kk * N; ws0[c * BK + kk] = pf[i]; }
        }
    }
    __syncthreads();

    for (int ch = 0; ch < NCH; ch++) {
        const float* cur = smem + WOFF + (ch & 1) * WSL;
        const bool more = (ch + 1) < NCH;
        if (more) {
            const float* wn = Wg + (size_t)(ch + 1) * BK * N;
#pragma unroll
            for (int i = 0; i < NLD; i++) {
                int idx = tid + 256 * i;
                if (idx < BK * N) pf[i] = wn[idx];
            }
        }
        const float* abase = Asm + ch * BK * APAD + wy * 4;
#pragma unroll
        for (int kk = 0; kk < BK; kk += 2) {
            float wv[CI][2];
#pragma unroll
            for (int c = 0; c < CI; c++) {
                // col may exceed N-1 (padded slot); values discarded in epilogue
                float2 v = *(const float2*)&cur[(lane + 32 * c) * BK + kk];
                wv[c][0] = v.x; wv[c][1] = v.y;
            }
            ulonglong2 a0 = *(const ulonglong2*)(abase + kk * APAD);
            ulonglong2 a1 = *(const ulonglong2*)(abase + (kk + 1) * APAD);
#pragma unroll
            for (int c = 0; c < CI; c++) {
                ull w0 = dup2(wv[c][0]);
                ull w1 = dup2(wv[c][1]);
                acc[0][c] = fma2(a0.x, w0, acc[0][c]);
                acc[1][c] = fma2(a0.y, w0, acc[1][c]);
                acc[0][c] = fma2(a1.x, w1, acc[0][c]);
                acc[1][c] = fma2(a1.y, w1, acc[1][c]);
            }
        }
        if (more) {
            float* nxt = smem + WOFF + ((ch + 1) & 1) * WSL;
#pragma unroll
            for (int i = 0; i < NLD; i++) {
                int idx = tid + 256 * i;
                if (idx < BK * N) { int kk = idx / N, c = idx - kk * N; nxt[c * BK + kk] = pf[i]; }
            }
            __syncthreads();   // single bar per chunk
        }
    }

#pragma unroll
    for (int c = 0; c < CI; c++) {
        int col = lane + 32 * c;
        if (col < N) {
            float bv = bg[col];
#pragma unroll
            for (int r = 0; r < 2; r++) {
                float lo, hi;
                unpack2(acc[r][c], lo, hi);
                lo += bv; hi += bv;
                if (RELU) { lo = fmaxf(lo, 0.0f); hi = fmaxf(hi, 0.0f); }
                int row = wy * 4 + 2 * r;
                if (TOGLOBAL) {
                    Gout[(size_t)row * N + col] = lo;
                    Gout[(size_t)(row + 1) * N + col] = hi;
                } else {
                    *(float2*)&Hsm[col * APAD + row] = make_float2(lo, hi);
                }
            }
        }
    }
}

__global__ __launch_bounds__(256, 4) void mlp_kernel(
    const float* __restrict__ x,
    const float* __restrict__ w1, const float* __restrict__ b1,
    const float* __restrict__ w2, const float* __restrict__ b2,
    const float* __restrict__ wl, const float* __restrict__ bl,
    float* __restrict__ logits) {
    extern __shared__ float smem[];
    const int tid = threadIdx.x;
    const int rowBase = blockIdx.x * TM;

    {
        const float4* xb = (const float4*)(x + (size_t)rowBase * D_IN);
        for (int it = tid; it < 32 * 50; it += 256) {
            int q = it >> 5, row = it & 31;
            float4 v = xb[row * 50 + q];
            float* p = smem + OFF_X + (4 * q) * APAD + row;
            p[0] = v.x; p[APAD] = v.y; p[2 * APAD] = v.z; p[3 * APAD] = v.w;
        }
    }
    // L1: weights in WS region (x live in OFF_X)
    layer<200, 100, 4, 10, OFF_WS, WSL12, true, false>(
        smem, smem + OFF_X, w1, b1, smem + OFF_H1, nullptr, tid);
    // L2: in-place on H1; weights in WS region
    layer<100, 100, 4, 10, OFF_WS, WSL12, true, false>(
        smem, smem + OFF_H1, w2, b2, smem + OFF_H1, nullptr, tid);
    // L3: weights double-buffered over dead XsT region
    layer<100, 200, 7, 10, OFF_X, WSL3, false, true>(
        smem, smem + OFF_H1, wl, bl, nullptr, logits + (size_t)rowBase * D_IN, tid);
}

// ---- sampler: one warp/row; k processed in PAIRS so the two shfl chains overlap ----
__device__ __forceinline__ void load8(float* dst, const float* src, bool act) {
    if (act) {
        float4 a = *(const float4*)src;
        float4 b = *(const float4*)(src + 4);
        dst[0] = a.x; dst[1] = a.y; dst[2] = a.z; dst[3] = a.w;
        dst[4] = b.x; dst[5] = b.y; dst[6] = b.z; dst[7] = b.w;
    } else {
#pragma unroll
        for (int i = 0; i < 8; i++) dst[i] = 0.5f;
    }
}

// elementwise: u[8] -> w[8] (in place), returns partial sum
__device__ __forceinline__ float gumbel8(float* u, const ull* Epk,
                                         ull C1, ull C2, ull C3, ull M1) {
    constexpr float EPSF = 1.1920929e-07f;
    ull sacc = 0ull;
#pragma unroll
    for (int j = 0; j < 4; j++) {
        float u0 = fmaxf(u[2 * j], EPSF);
        float u1 = fmaxf(u[2 * j + 1], EPSF);
        float l0 = flg2(u0);
        float l1 = flg2(u1);
        ull upk = pack2(u0, u1);
        ull xm = add2(upk, M1);                    // u-1, exact near 1
        ull q = fma2(xm, fma2(xm, C3, C2), C1);
        ull pp = mul2(xm, q);                      // accurate log2(1+xm)
        float p0, p1;
        unpack2(pp, p0, p1);
        float t0 = (u0 > 0.99f) ? p0 : l0;
        float t1 = (u1 > 0.99f) ? p1 : l1;
        ull tt = pack2(t0, t1);
        ull t2 = mul2(tt, tt);
        float s0, s1;
        unpack2(t2, s0, s1);
        ull rr = pack2(frcp(s0), frcp(s1));
        ull w = mul2(Epk[j], rr);                  // E / lg2(u)^2
        float w0, w1;
        unpack2(w, w0, w1);
        u[2 * j] = w0; u[2 * j + 1] = w1;
        sacc = add2(sacc, w);
    }
    float sl, sh;
    unpack2(sacc, sl, sh);
    return sl + sh;
}

__global__ __launch_bounds__(256, 4) void sample_kernel(
    const float* __restrict__ x, const float* __restrict__ uniform,
    const float* __restrict__ logits,
    const float* __restrict__ wo, const float* __restrict__ bo,
    float* __restrict__ preds, float* __restrict__ samples) {
    const int b = (blockIdx.x * 256 + threadIdx.x) >> 5;
    const int lane = threadIdx.x & 31;
    const bool act = lane < 25;
    const int d0 = 8 * lane;

    const ull C1 = pack2(1.44269504f, 1.44269504f);
    const ull C2 = pack2(-0.72134752f, -0.72134752f);
    const ull C3 = pack2(0.48089835f, 0.48089835f);
    const ull M1 = pack2(-1.0f, -1.0f);

    ull Epk[4];
    float smp[8];
    {
        float lg[8];
        if (act) load8(lg, &logits[(size_t)b * D_IN + d0], true);
        else {
#pragma unroll
            for (int i = 0; i < 8; i++) lg[i] = -1e30f;
        }
        float m = lg[0];
#pragma unroll
        for (int i = 1; i < 8; i++) m = fmaxf(m, lg[i]);
#pragma unroll
        for (int off = 16; off > 0; off >>= 1)
            m = fmaxf(m, __shfl_xor_sync(0xffffffffu, m, off));
#pragma unroll
        for (int j = 0; j < 4; j++) {
            float e0 = act ? __expf(2.0f * (lg[2 * j] - m)) : 0.0f;
            float e1 = act ? __expf(2.0f * (lg[2 * j + 1] - m)) : 0.0f;
            Epk[j] = pack2(e0, e1);
        }
#pragma unroll
        for (int i = 0; i < 8; i++) smp[i] = 0.0f;
    }

    const float* up = uniform + (size_t)b * (K_SAMP * D_IN) + d0;
    float ua[8], ub[8];
    load8(ua, up, act);
    load8(ub, up + D_IN, act);

#pragma unroll
    for (int kp = 0; kp < K_SAMP / 2; kp++) {
        float na[8], nb[8];
        if (kp < K_SAMP / 2 - 1) {
            load8(na, up + (2 * kp + 2) * D_IN, act);
            load8(nb, up + (2 * kp + 3) * D_IN, act);
        }
        float sA = gumbel8(ua, Epk, C1, C2, C3, M1);
        float sB = gumbel8(ub, Epk, C1, C2, C3, M1);
#pragma unroll
        for (int off = 16; off > 0; off >>= 1) {
            sA += __shfl_xor_sync(0xffffffffu, sA, off);
            sB += __shfl_xor_sync(0xffffffffu, sB, off);
        }
        float ia = frcp(sA), ib = frcp(sB);
#pragma unroll
        for (int i = 0; i < 8; i++) {
            smp[i] = fmaxf(smp[i], ua[i] * ia);
            smp[i] = fmaxf(smp[i], ub[i] * ib);
        }
        if (kp < K_SAMP / 2 - 1) {
#pragma unroll
            for (int i = 0; i < 8; i++) { ua[i] = na[i]; ub[i] = nb[i]; }
        }
    }

    if (act) {
        *(float4*)&samples[(size_t)b * D_IN + d0] =
            make_float4(smp[0], smp[1], smp[2], smp[3]);
        *(float4*)&samples[(size_t)b * D_IN + d0 + 4] =
            make_float4(smp[4], smp[5], smp[6], smp[7]);
    }

    float p0 = 0.0f, p1 = 0.0f;
    if (act) {
        float xv[8];
        load8(xv, &x[(size_t)b * D_IN + d0], true);
#pragma unroll
        for (int i = 0; i < 8; i += 2) {
            float4 w4 = *(const float4*)&wo[(d0 + i) * 2];
            float a0 = xv[i] * smp[i], a1 = xv[i + 1] * smp[i + 1];
            p0 += a0 * w4.x + a1 * w4.z;
            p1 += a0 * w4.y + a1 * w4.w;
        }
    }
#pragma unroll
    for (int off = 16; off > 0; off >>= 1) {
        p0 += __shfl_xor_sync(0xffffffffu, p0, off);
        p1 += __shfl_xor_sync(0xffffffffu, p1, off);
    }
    if (lane == 0) {
        p0 += bo[0]; p1 += bo[1];
        float mm = fmaxf(p0, p1);
        float e0 = __expf(p0 - mm), e1 = __expf(p1 - mm);
        float is = 1.0f / (e0 + e1);
        preds[(size_t)b * 2 + 0] = e0 * is;
        preds[(size_t)b * 2 + 1] = e1 * is;
    }
}

extern "C" void kernel_launch(void* const* d_in, const int* in_sizes, int n_in,
                              void* d_out, int out_size) {
    const float* x  = (const float*)d_in[0];
    const float* un = (const float*)d_in[1];
    const float* w1 = (const float*)d_in[2];
    const float* b1 = (const float*)d_in[3];
    const float* w2 = (const float*)d_in[4];
    const float* b2 = (const float*)d_in[5];
    const float* wl = (const float*)d_in[6];
    const float* bl = (const float*)d_in[7];
    const float* wo = (const float*)d_in[8];
    const float* bo = (const float*)d_in[9];
    float* out = (float*)d_out;

    float* lgts;
    cudaGetSymbolAddress((void**)&lgts, g_logits);

    const int smem_bytes = SMEM_FLOATS * (int)sizeof(float);  // 53440
    cudaFuncSetAttribute(mlp_kernel, cudaFuncAttributeMaxDynamicSharedMemorySize, smem_bytes);

    mlp_kernel<<<B_ROWS / TM, 256, smem_bytes>>>(x, w1, b1, w2, b2, wl, bl, lgts);
    sample_kernel<<<B_ROWS / 8, 256>>>(x, un, lgts, wo, bo,
                                       out, out + (size_t)B_ROWS * 2);
}

// round 13
// speedup vs baseline: 1.0108x; 1.0108x over previous
#include <cuda_runtime.h>

#define B_ROWS 32768
#define D_IN   200
#define K_SAMP 10
#define TM     64
#define APAD   68

__device__ float g_logits[(size_t)B_ROWS * D_IN];

// smem (floats): XsT[200][68] | H1T[100][68] (L2 in-place) | WS 2 slots of 2240
#define OFF_X  0
#define OFF_H1 (200 * APAD)               // 13600
#define OFF_WS (OFF_H1 + 100 * APAD)      // 20400
#define WSLOT  2240
#define SMEM_FLOATS (OFF_WS + 2 * WSLOT)  // 24880 floats = 99520 B -> 2 CTAs/SM

typedef unsigned long long ull;

__device__ __forceinline__ ull pack2(float lo, float hi) {
    ull r; asm("mov.b64 %0, {%1, %2};" : "=l"(r) : "f"(lo), "f"(hi)); return r;
}
__device__ __forceinline__ ull dup2(float w) {
    ull r; asm("mov.b64 %0, {%1, %1};" : "=l"(r) : "f"(w)); return r;
}
__device__ __forceinline__ void unpack2(ull v, float& lo, float& hi) {
    asm("mov.b64 {%0, %1}, %2;" : "=f"(lo), "=f"(hi) : "l"(v));
}
__device__ __forceinline__ ull fma2(ull a, ull b, ull c) {
    ull d; asm("fma.rn.f32x2 %0, %1, %2, %3;" : "=l"(d) : "l"(a), "l"(b), "l"(c)); return d;
}
__device__ __forceinline__ ull mul2(ull a, ull b) {
    ull d; asm("mul.rn.f32x2 %0, %1, %2;" : "=l"(d) : "l"(a), "l"(b)); return d;
}
__device__ __forceinline__ ull add2(ull a, ull b) {
    ull d; asm("add.rn.f32x2 %0, %1, %2;" : "=l"(d) : "l"(a), "l"(b)); return d;
}
__device__ __forceinline__ float frcp(float x) {
    float r; asm("rcp.approx.f32 %0, %1;" : "=f"(r) : "f"(x)); return r;
}
__device__ __forceinline__ float flg2(float x) {
    float r; asm("lg2.approx.f32 %0, %1;" : "=f"(r) : "f"(x)); return r;
}

// ---- one layer over 64 rows; A in smem [K][APAD]; 8 warps x 8 rows ----
// Weight slots: interleaved k-pair layout ws[(kk>>1)*2N + 2*col + (kk&1)]
// -> lane reads float2 {w[kk][col], w[kk+1][col]} at stride 8B: conflict-free.
template <int K, int N, int CI, int BK, bool RELU, bool TOGLOBAL>
__device__ __forceinline__ void layer(float* smem, const float* Asm,
                                      const float* __restrict__ Wg,
                                      const float* __restrict__ bg,
                                      float* Hsm, float* __restrict__ Gout,
                                      int tid) {
    static_assert(BK % 2 == 0, "BK even");
    static_assert((BK / 2) * 2 * N + 2 * (32 * CI - 1) + 1 < WSLOT + 2 * N, "slot");
    constexpr int NLD = (BK * N + 255) / 256;
    constexpr int NCH = K / BK;
    const int lane = tid & 31;
    const int wy = tid >> 5;   // rows [8wy, 8wy+8)

    ull acc[4][CI];
#pragma unroll
    for (int r = 0; r < 4; r++)
#pragma unroll
        for (int c = 0; c < CI; c++) acc[r][c] = 0ull;

    float pf[NLD];
#pragma unroll
    for (int i = 0; i < NLD; i++) {
        int idx = tid + 256 * i;
        if (idx < BK * N) pf[i] = Wg[idx];
    }
    __syncthreads();   // prev layer done with WS & Asm visible
    {
        float* ws0 = smem + OFF_WS;
#pragma unroll
        for (int i = 0; i < NLD; i++) {
            int idx = tid + 256 * i;
            if (idx < BK * N) {
                int kk = idx / N, c = idx - kk * N;
                ws0[(kk >> 1) * (2 * N) + 2 * c + (kk & 1)] = pf[i];
            }
        }
    }
    __syncthreads();

    for (int ch = 0; ch < NCH; ch++) {
        const float* cur = smem + OFF_WS + (ch & 1) * WSLOT;
        const bool more = (ch + 1) < NCH;
        if (more) {
            const float* wn = Wg + (size_t)(ch + 1) * BK * N;
#pragma unroll
            for (int i = 0; i < NLD; i++) {
                int idx = tid + 256 * i;
                if (idx < BK * N) pf[i] = wn[idx];
            }
        }
        const float* abase = Asm + ch * BK * APAD + wy * 8;
#pragma unroll
        for (int kk = 0; kk < BK; kk += 2) {
            float2 wv[CI];
#pragma unroll
            for (int c = 0; c < CI; c++)
                wv[c] = *(const float2*)&cur[(kk >> 1) * (2 * N) + 2 * (lane + 32 * c)];
            const float* ar0 = abase + kk * APAD;
            const float* ar1 = abase + (kk + 1) * APAD;
            ulonglong2 a01 = *(const ulonglong2*)ar0;
            ulonglong2 a23 = *(const ulonglong2*)(ar0 + 4);
            ulonglong2 b01 = *(const ulonglong2*)ar1;
            ulonglong2 b23 = *(const ulonglong2*)(ar1 + 4);
#pragma unroll
            for (int c = 0; c < CI; c++) {
                ull w0 = dup2(wv[c].x);
                ull w1 = dup2(wv[c].y);
                acc[0][c] = fma2(a01.x, w0, acc[0][c]);
                acc[1][c] = fma2(a01.y, w0, acc[1][c]);
                acc[2][c] = fma2(a23.x, w0, acc[2][c]);
                acc[3][c] = fma2(a23.y, w0, acc[3][c]);
                acc[0][c] = fma2(b01.x, w1, acc[0][c]);
                acc[1][c] = fma2(b01.y, w1, acc[1][c]);
                acc[2][c] = fma2(b23.x, w1, acc[2][c]);
                acc[3][c] = fma2(b23.y, w1, acc[3][c]);
            }
        }
        if (more) {
            float* nxt = smem + OFF_WS + ((ch + 1) & 1) * WSLOT;
#pragma unroll
            for (int i = 0; i < NLD; i++) {
                int idx = tid + 256 * i;
                if (idx < BK * N) {
                    int kk = idx / N, c = idx - kk * N;
                    nxt[(kk >> 1) * (2 * N) + 2 * c + (kk & 1)] = pf[i];
                }
            }
            __syncthreads();
        }
    }

#pragma unroll
    for (int c = 0; c < CI; c++) {
        int col = lane + 32 * c;
        if (col < N) {
            float bv = bg[col];
#pragma unroll
            for (int r = 0; r < 4; r++) {
                float lo, hi;
                unpack2(acc[r][c], lo, hi);
                lo += bv; hi += bv;
                if (RELU) { lo = fmaxf(lo, 0.0f); hi = fmaxf(hi, 0.0f); }
                int row = wy * 8 + 2 * r;
                if (TOGLOBAL) {
                    Gout[(size_t)row * N + col] = lo;
                    Gout[(size_t)(row + 1) * N + col] = hi;
                } else {
                    *(float2*)&Hsm[col * APAD + row] = make_float2(lo, hi);
                }
            }
        }
    }
}

__global__ __launch_bounds__(256, 2) void mlp_kernel(
    const float* __restrict__ x,
    const float* __restrict__ w1, const float* __restrict__ b1,
    const float* __restrict__ w2, const float* __restrict__ b2,
    const float* __restrict__ wl, const float* __restrict__ bl,
    float* __restrict__ logits) {
    extern __shared__ float smem[];
    const int tid = threadIdx.x;
    const int rowBase = blockIdx.x * TM;

    {
        const float4* xb = (const float4*)(x + (size_t)rowBase * D_IN);
        for (int it = tid; it < 64 * 50; it += 256) {
            int q = it >> 6, row = it & 63;
            float4 v = xb[row * 50 + q];
            float* p = smem + OFF_X + (4 * q) * APAD + row;
            p[0] = v.x; p[APAD] = v.y; p[2 * APAD] = v.z; p[3 * APAD] = v.w;
        }
    }
    layer<200, 100, 4, 10, true, false>(smem, smem + OFF_X, w1, b1, smem + OFF_H1, nullptr, tid);
    layer<100, 100, 4, 10, true, false>(smem, smem + OFF_H1, w2, b2, smem + OFF_H1, nullptr, tid);
    layer<100, 200, 7, 10, false, true>(smem, smem + OFF_H1, wl, bl, nullptr,
                                        logits + (size_t)rowBase * D_IN, tid);
}

// ---- sampler (R12, unchanged) ----
__device__ __forceinline__ void load8(float* dst, const float* src, bool act) {
    if (act) {
        float4 a = *(const float4*)src;
        float4 b = *(const float4*)(src + 4);
        dst[0] = a.x; dst[1] = a.y; dst[2] = a.z; dst[3] = a.w;
        dst[4] = b.x; dst[5] = b.y; dst[6] = b.z; dst[7] = b.w;
    } else {
#pragma unroll
        for (int i = 0; i < 8; i++) dst[i] = 0.5f;
    }
}

__device__ __forceinline__ float gumbel8(float* u, const ull* Epk,
                                         ull C1, ull C2, ull C3, ull M1) {
    constexpr float EPSF = 1.1920929e-07f;
    ull sacc = 0ull;
#pragma unroll
    for (int j = 0; j < 4; j++) {
        float u0 = fmaxf(u[2 * j], EPSF);
        float u1 = fmaxf(u[2 * j + 1], EPSF);
        float l0 = flg2(u0);
        float l1 = flg2(u1);
        ull upk = pack2(u0, u1);
        ull xm = add2(upk, M1);
        ull q = fma2(xm, fma2(xm, C3, C2), C1);
        ull pp = mul2(xm, q);
        float p0, p1;
        unpack2(pp, p0, p1);
        float t0 = (u0 > 0.99f) ? p0 : l0;
        float t1 = (u1 > 0.99f) ? p1 : l1;
        ull tt = pack2(t0, t1);
        ull t2 = mul2(tt, tt);
        float s0, s1;
        unpack2(t2, s0, s1);
        ull rr = pack2(frcp(s0), frcp(s1));
        ull w = mul2(Epk[j], rr);
        float w0, w1;
        unpack2(w, w0, w1);
        u[2 * j] = w0; u[2 * j + 1] = w1;
        sacc = add2(sacc, w);
    }
    float sl, sh;
    unpack2(sacc, sl, sh);
    return sl + sh;
}

__global__ __launch_bounds__(256, 4) void sample_kernel(
    const float* __restrict__ x, const float* __restrict__ uniform,
    const float* __restrict__ logits,
    const float* __restrict__ wo, const float* __restrict__ bo,
    float* __restrict__ preds, float* __restrict__ samples) {
    const int b = (blockIdx.x * 256 + threadIdx.x) >> 5;
    const int lane = threadIdx.x & 31;
    const bool act = lane < 25;
    const int d0 = 8 * lane;

    const ull C1 = pack2(1.44269504f, 1.44269504f);
    const ull C2 = pack2(-0.72134752f, -0.72134752f);
    const ull C3 = pack2(0.48089835f, 0.48089835f);
    const ull M1 = pack2(-1.0f, -1.0f);

    ull Epk[4];
    float smp[8];
    {
        float lg[8];
        if (act) load8(lg, &logits[(size_t)b * D_IN + d0], true);
        else {
#pragma unroll
            for (int i = 0; i < 8; i++) lg[i] = -1e30f;
        }
        float m = lg[0];
#pragma unroll
        for (int i = 1; i < 8; i++) m = fmaxf(m, lg[i]);
#pragma unroll
        for (int off = 16; off > 0; off >>= 1)
            m = fmaxf(m, __shfl_xor_sync(0xffffffffu, m, off));
#pragma unroll
        for (int j = 0; j < 4; j++) {
            float e0 = act ? __expf(2.0f * (lg[2 * j] - m)) : 0.0f;
            float e1 = act ? __expf(2.0f * (lg[2 * j + 1] - m)) : 0.0f;
            Epk[j] = pack2(e0, e1);
        }
#pragma unroll
        for (int i = 0; i < 8; i++) smp[i] = 0.0f;
    }

    const float* up = uniform + (size_t)b * (K_SAMP * D_IN) + d0;
    float ua[8], ub[8];
    load8(ua, up, act);
    load8(ub, up + D_IN, act);

#pragma unroll
    for (int kp = 0; kp < K_SAMP / 2; kp++) {
        float na[8], nb[8];
        if (kp < K_SAMP / 2 - 1) {
            load8(na, up + (2 * kp + 2) * D_IN, act);
            load8(nb, up + (2 * kp + 3) * D_IN, act);
        }
        float sA = gumbel8(ua, Epk, C1, C2, C3, M1);
        float sB = gumbel8(ub, Epk, C1, C2, C3, M1);
#pragma unroll
        for (int off = 16; off > 0; off >>= 1) {
            sA += __shfl_xor_sync(0xffffffffu, sA, off);
            sB += __shfl_xor_sync(0xffffffffu, sB, off);
        }
        float ia = frcp(sA), ib = frcp(sB);
#pragma unroll
        for (int i = 0; i < 8; i++) {
            smp[i] = fmaxf(smp[i], ua[i] * ia);
            smp[i] = fmaxf(smp[i], ub[i] * ib);
        }
        if (kp < K_SAMP / 2 - 1) {
#pragma unroll
            for (int i = 0; i < 8; i++) { ua[i] = na[i]; ub[i] = nb[i]; }
        }
    }

    if (act) {
        *(float4*)&samples[(size_t)b * D_IN + d0] =
            make_float4(smp[0], smp[1], smp[2], smp[3]);
        *(float4*)&samples[(size_t)b * D_IN + d0 + 4] =
            make_float4(smp[4], smp[5], smp[6], smp[7]);
    }

    float p0 = 0.0f, p1 = 0.0f;
    if (act) {
        float xv[8];
        load8(xv, &x[(size_t)b * D_IN + d0], true);
#pragma unroll
        for (int i = 0; i < 8; i += 2) {
            float4 w4 = *(const float4*)&wo[(d0 + i) * 2];
            float a0 = xv[i] * smp[i], a1 = xv[i + 1] * smp[i + 1];
            p0 += a0 * w4.x + a1 * w4.z;
            p1 += a0 * w4.y + a1 * w4.w;
        }
    }
#pragma unroll
    for (int off = 16; off > 0; off >>= 1) {
        p0 += __shfl_xor_sync(0xffffffffu, p0, off);
        p1 += __shfl_xor_sync(0xffffffffu, p1, off);
    }
    if (lane == 0) {
        p0 += bo[0]; p1 += bo[1];
        float mm = fmaxf(p0, p1);
        float e0 = __expf(p0 - mm), e1 = __expf(p1 - mm);
        float is = 1.0f / (e0 + e1);
        preds[(size_t)b * 2 + 0] = e0 * is;
        preds[(size_t)b * 2 + 1] = e1 * is;
    }
}

extern "C" void kernel_launch(void* const* d_in, const int* in_sizes, int n_in,
                              void* d_out, int out_size) {
    const float* x  = (const float*)d_in[0];
    const float* un = (const float*)d_in[1];
    const float* w1 = (const float*)d_in[2];
    const float* b1 = (const float*)d_in[3];
    const float* w2 = (const float*)d_in[4];
    const float* b2 = (const float*)d_in[5];
    const float* wl = (const float*)d_in[6];
    const float* bl = (const float*)d_in[7];
    const float* wo = (const float*)d_in[8];
    const float* bo = (const float*)d_in[9];
    float* out = (float*)d_out;

    float* lgts;
    cudaGetSymbolAddress((void**)&lgts, g_logits);

    const int smem_bytes = SMEM_FLOATS * (int)sizeof(float);  // 99520
    cudaFuncSetAttribute(mlp_kernel, cudaFuncAttributeMaxDynamicSharedMemorySize, smem_bytes);

    mlp_kernel<<<B_ROWS / TM, 256, smem_bytes>>>(x, w1, b1, w2, b2, wl, bl, lgts);
    sample_kernel<<<B_ROWS / 8, 256>>>(x, un, lgts, wo, bo,
                                       out, out + (size_t)B_ROWS * 2);
}